// round 3
// baseline (speedup 1.0000x reference)
#include <cuda_runtime.h>
#include <cuda_bf16.h>
#include <cstdint>

#define N_NODES 100000
#define E_EDGES 1000000
#define IN_F    128
#define OUT_C   64      // NUM_HEADS * OUT_FEAT
#define NH      4
#define ALPHA   0.2f

// ---------------- scratch (static device arrays; no allocation) ----------------
__device__ float g_Wh[(size_t)N_NODES * OUT_C];   // 25.6 MB
__device__ float g_sa[(size_t)N_NODES * NH];      // s_src per node
__device__ float g_sb[(size_t)N_NODES * NH];      // s_dst per node
__device__ int   g_is64;                          // edge_index dtype flag

// ---------------- dtype autodetect for edge_index ----------------
__global__ void detect_kernel(const void* ei)
{
    // If the buffer really holds int64 indices, every 8-byte value is in
    // [0, N_NODES). If it holds int32 pairs, the high word of most 8-byte
    // values is a second (generally nonzero) index -> value >= 2^32.
    const long long* p = (const long long*)ei;
    int ok = 1;
    for (int i = 0; i < 256; i++) {
        long long v = p[i];
        if (v < 0 || v >= N_NODES) ok = 0;
    }
    g_is64 = ok;
}

// ---------------- GEMM: Wh = h @ W, fused s_src/s_dst epilogue ----------------
#define BR 256
#define TR 8
#define TC 8
#define GEMM_SMEM_BYTES ((IN_F * BR + IN_F * OUT_C) * 4)   // 160 KB

__global__ __launch_bounds__(256, 1)
void gemm_kernel(const float* __restrict__ h,
                 const float* __restrict__ W,
                 const float* __restrict__ a_src,
                 const float* __restrict__ a_dst)
{
    extern __shared__ float smem[];
    float* As = smem;                 // [IN_F][BR]  (k-major, transposed)
    float* Bs = smem + IN_F * BR;     // [IN_F][OUT_C]

    const int tid  = threadIdx.x;
    const int row0 = blockIdx.x * BR;

    // ---- load A tile (each thread owns one full row of h), transpose into As ----
    {
        const int row = row0 + tid;
        if (row < N_NODES) {
            const float4* hp = (const float4*)(h + (size_t)row * IN_F);
            #pragma unroll
            for (int k4 = 0; k4 < IN_F / 4; k4++) {
                float4 v = hp[k4];
                As[(k4 * 4 + 0) * BR + tid] = v.x;
                As[(k4 * 4 + 1) * BR + tid] = v.y;
                As[(k4 * 4 + 2) * BR + tid] = v.z;
                As[(k4 * 4 + 3) * BR + tid] = v.w;
            }
        } else {
            #pragma unroll
            for (int k = 0; k < IN_F; k++) As[k * BR + tid] = 0.0f;
        }
    }
    // ---- load W (same layout as global: [k][col]) ----
    {
        const float4* wp = (const float4*)W;
        float4*       bp = (float4*)Bs;
        #pragma unroll
        for (int i = 0; i < (IN_F * OUT_C / 4) / 256; i++)
            bp[tid + i * 256] = wp[tid + i * 256];
    }
    __syncthreads();

    const int tc = tid & 7;    // col group (8 cols)
    const int tr = tid >> 3;   // row group (8 rows)

    float acc[TR][TC];
    #pragma unroll
    for (int i = 0; i < TR; i++)
        #pragma unroll
        for (int j = 0; j < TC; j++) acc[i][j] = 0.0f;

    #pragma unroll 8
    for (int k = 0; k < IN_F; k++) {
        float4 a0 = *(const float4*)&As[k * BR + tr * TR];
        float4 a1 = *(const float4*)&As[k * BR + tr * TR + 4];
        float4 b0 = *(const float4*)&Bs[k * OUT_C + tc * TC];
        float4 b1 = *(const float4*)&Bs[k * OUT_C + tc * TC + 4];
        float av[TR] = {a0.x, a0.y, a0.z, a0.w, a1.x, a1.y, a1.z, a1.w};
        float bv[TC] = {b0.x, b0.y, b0.z, b0.w, b1.x, b1.y, b1.z, b1.w};
        #pragma unroll
        for (int i = 0; i < TR; i++)
            #pragma unroll
            for (int j = 0; j < TC; j++)
                acc[i][j] = fmaf(av[i], bv[j], acc[i][j]);
    }

    // attention-vector coefficients for this thread's 8 columns
    float asv[TC], adv[TC];
    {
        float4 s0 = *(const float4*)&a_src[tc * TC];
        float4 s1 = *(const float4*)&a_src[tc * TC + 4];
        float4 d0 = *(const float4*)&a_dst[tc * TC];
        float4 d1 = *(const float4*)&a_dst[tc * TC + 4];
        asv[0]=s0.x; asv[1]=s0.y; asv[2]=s0.z; asv[3]=s0.w;
        asv[4]=s1.x; asv[5]=s1.y; asv[6]=s1.z; asv[7]=s1.w;
        adv[0]=d0.x; adv[1]=d0.y; adv[2]=d0.z; adv[3]=d0.w;
        adv[4]=d1.x; adv[5]=d1.y; adv[6]=d1.z; adv[7]=d1.w;
    }

    #pragma unroll
    for (int i = 0; i < TR; i++) {
        float ps = 0.0f, pd = 0.0f;
        #pragma unroll
        for (int j = 0; j < TC; j++) {
            ps = fmaf(acc[i][j], asv[j], ps);
            pd = fmaf(acc[i][j], adv[j], pd);
        }
        // combine the two col-groups of the same head (lanes tc, tc^1 share tr)
        ps += __shfl_xor_sync(0xffffffffu, ps, 1);
        pd += __shfl_xor_sync(0xffffffffu, pd, 1);

        const int row = row0 + tr * TR + i;
        if (row < N_NODES) {
            float* wout = &g_Wh[(size_t)row * OUT_C + tc * TC];
            *(float4*)&wout[0] = make_float4(acc[i][0], acc[i][1], acc[i][2], acc[i][3]);
            *(float4*)&wout[4] = make_float4(acc[i][4], acc[i][5], acc[i][6], acc[i][7]);
            if ((tc & 1) == 0) {
                g_sa[(size_t)row * NH + (tc >> 1)] = ps;
                g_sb[(size_t)row * NH + (tc >> 1)] = pd;
            }
        }
    }
}

// ---------------- edge kernel: 16 threads per edge, one float4 each ----------------
__global__ __launch_bounds__(256)
void edge_kernel(const void* __restrict__ ei_raw, float* __restrict__ out)
{
    const long long gt = (long long)blockIdx.x * blockDim.x + threadIdx.x;
    const int edge = (int)(gt >> 4);
    const int l    = (int)(gt & 15);
    if (edge >= E_EDGES) return;

    int src, dst;
    if (g_is64) {
        const long long* ei = (const long long*)ei_raw;
        src = (int)__ldg(&ei[edge]);
        dst = (int)__ldg(&ei[(size_t)E_EDGES + edge]);
    } else {
        const int* ei = (const int*)ei_raw;
        src = __ldg(&ei[edge]);
        dst = __ldg(&ei[(size_t)E_EDGES + edge]);
    }
    // safety clamp: a wrong dtype guess must degrade to wrong values, not a fault
    src = min(max(src, 0), N_NODES - 1);
    dst = min(max(dst, 0), N_NODES - 1);

    // attention logits from precomputed per-node dots
    const float4 ss = *(const float4*)&g_sa[(size_t)src * NH];
    const float4 sd = *(const float4*)&g_sb[(size_t)dst * NH];
    float e0 = ss.x + sd.x, e1 = ss.y + sd.y, e2 = ss.z + sd.z, e3 = ss.w + sd.w;
    e0 = (e0 >= 0.0f) ? e0 : ALPHA * e0;
    e1 = (e1 >= 0.0f) ? e1 : ALPHA * e1;
    e2 = (e2 >= 0.0f) ? e2 : ALPHA * e2;
    e3 = (e3 >= 0.0f) ? e3 : ALPHA * e3;

    // softmax over the 4 heads (axis=1 of [E,H], faithful to reference)
    const float m  = fmaxf(fmaxf(e0, e1), fmaxf(e2, e3));
    const float x0 = __expf(e0 - m), x1 = __expf(e1 - m);
    const float x2 = __expf(e2 - m), x3 = __expf(e3 - m);
    const float inv = 1.0f / (x0 + x1 + x2 + x3);

    const int hh = l >> 2;                         // head for cols [l*4, l*4+4)
    float att = (hh == 0) ? x0 : (hh == 1) ? x1 : (hh == 2) ? x2 : x3;
    att *= inv;

    const float4 w = *(const float4*)&g_Wh[(size_t)src * OUT_C + l * 4];
    float* dptr = out + (size_t)dst * OUT_C + l * 4;
    asm volatile("red.global.add.v4.f32 [%0], {%1,%2,%3,%4};"
                 :: "l"(dptr), "f"(w.x * att), "f"(w.y * att),
                    "f"(w.z * att), "f"(w.w * att)
                 : "memory");
}

// ---------------- final ReLU (in place on d_out) ----------------
__global__ __launch_bounds__(256)
void relu_kernel(float4* __restrict__ out, int n4)
{
    const int i = blockIdx.x * blockDim.x + threadIdx.x;
    if (i < n4) {
        float4 v = out[i];
        v.x = fmaxf(v.x, 0.0f); v.y = fmaxf(v.y, 0.0f);
        v.z = fmaxf(v.z, 0.0f); v.w = fmaxf(v.w, 0.0f);
        out[i] = v;
    }
}

// ---------------- launch ----------------
extern "C" void kernel_launch(void* const* d_in, const int* in_sizes, int n_in,
                              void* d_out, int out_size)
{
    // size-based input identification (robust to ordering surprises)
    const float* h     = nullptr;
    const void*  ei    = nullptr;
    const float* W     = nullptr;
    const float* a_src = nullptr;
    const float* a_dst = nullptr;
    for (int i = 0; i < n_in; i++) {
        const int s = in_sizes[i];
        if      (s == N_NODES * IN_F)  h  = (const float*)d_in[i];
        else if (s == 2 * E_EDGES)     ei = d_in[i];
        else if (s == IN_F * OUT_C)    W  = (const float*)d_in[i];
        else if (s == OUT_C) {
            if (!a_src) a_src = (const float*)d_in[i];
            else        a_dst = (const float*)d_in[i];
        }
    }
    // positional fallback (metadata order: h, edge_index, W, a_src, a_dst)
    if (!h || !ei || !W || !a_src || !a_dst) {
        h     = (const float*)d_in[0];
        ei    = d_in[1];
        W     = (const float*)d_in[2];
        a_src = (const float*)d_in[3];
        a_dst = (const float*)d_in[4];
    }
    float* out = (float*)d_out;

    detect_kernel<<<1, 1>>>(ei);

    // zero the accumulator (d_out is poisoned before timing)
    cudaMemsetAsync(out, 0, (size_t)N_NODES * OUT_C * sizeof(float), 0);

    cudaFuncSetAttribute(gemm_kernel,
                         cudaFuncAttributeMaxDynamicSharedMemorySize,
                         GEMM_SMEM_BYTES);

    gemm_kernel<<<(N_NODES + BR - 1) / BR, 256, GEMM_SMEM_BYTES>>>(h, W, a_src, a_dst);

    const long long ethreads = (long long)E_EDGES * 16;
    edge_kernel<<<(int)((ethreads + 255) / 256), 256>>>(ei, out);

    const int n4 = N_NODES * OUT_C / 4;
    relu_kernel<<<(n4 + 255) / 256, 256>>>((float4*)out, n4);
}

// round 4
// speedup vs baseline: 1.0793x; 1.0793x over previous
#include <cuda_runtime.h>
#include <cuda_fp16.h>
#include <mma.h>
#include <cstdint>

using namespace nvcuda;

#define N_NODES 100000
#define E_EDGES 1000000
#define IN_F    128
#define OUT_C   64      // NUM_HEADS * OUT_FEAT
#define NH      4
#define ALPHA   0.2f

// ---------------- scratch (static device arrays; no allocation) ----------------
__device__ __half g_Wh[(size_t)N_NODES * OUT_C];  // 12.8 MB (fp16 messages)
__device__ float  g_sa[(size_t)N_NODES * NH];     // s_src per node (fp32)
__device__ float  g_sb[(size_t)N_NODES * NH];     // s_dst per node (fp32)
__device__ int    g_is64;                         // edge_index dtype flag

// ---------------- dtype autodetect for edge_index ----------------
__global__ void detect_kernel(const void* ei)
{
    const long long* p = (const long long*)ei;
    int ok = 1;
    for (int i = 0; i < 256; i++) {
        long long v = p[i];
        if (v < 0 || v >= N_NODES) ok = 0;
    }
    g_is64 = ok;
}

// ---------------- GEMM: Wh = h @ W via split-fp16 3xHMMA, fused epilogue ------
// block: 256 threads (8 warps), tile 128 rows x 64 cols, K=128 staged once.
#define GR   128
#define LDA  136            // half elements (pad vs 128)
#define LDB  72             // half elements (pad vs 64)
#define LDC  68             // float elements (pad vs 64)

#define SM_AHI 0
#define SM_ALO (SM_AHI + GR * LDA * 2)            // 34816
#define SM_BHI (SM_ALO + GR * LDA * 2)            // 69632
#define SM_BLO (SM_BHI + IN_F * LDB * 2)          // 88064
#define GEMM_SMEM_BYTES (SM_BLO + IN_F * LDB * 2) // 106496

__global__ __launch_bounds__(256)
void gemm_kernel(const float* __restrict__ h,
                 const float* __restrict__ W,
                 const float* __restrict__ a_src,
                 const float* __restrict__ a_dst)
{
    extern __shared__ char smem[];
    __half* Ahi = (__half*)(smem + SM_AHI);
    __half* Alo = (__half*)(smem + SM_ALO);
    __half* Bhi = (__half*)(smem + SM_BHI);
    __half* Blo = (__half*)(smem + SM_BLO);
    float*  Cs  = (float*)smem;                   // aliases Ahi/Alo after MMA

    const int tid  = threadIdx.x;
    const int wid  = tid >> 5;
    const int row0 = blockIdx.x * GR;

    // ---- stage A: thread t handles row t/2, cols (t&1)*64..+63 ----
    {
        const int row  = row0 + (tid >> 1);
        const int cbase = (tid & 1) * 64;
        __half* ahp = &Ahi[(tid >> 1) * LDA + cbase];
        __half* alp = &Alo[(tid >> 1) * LDA + cbase];
        if (row < N_NODES) {
            const float4* hp = (const float4*)(h + (size_t)row * IN_F + cbase);
            #pragma unroll
            for (int i = 0; i < 16; i++) {
                float4 v = hp[i];
                float vv[4] = {v.x, v.y, v.z, v.w};
                #pragma unroll
                for (int j = 0; j < 4; j++) {
                    __half hi = __float2half_rn(vv[j]);
                    __half lo = __float2half_rn(vv[j] - __half2float(hi));
                    ahp[i * 4 + j] = hi;
                    alp[i * 4 + j] = lo;
                }
            }
        } else {
            #pragma unroll
            for (int i = 0; i < 64; i++) { ahp[i] = __float2half_rn(0.f); alp[i] = __float2half_rn(0.f); }
        }
    }
    // ---- stage B: 8192 floats, thread t handles 32 consecutive ----
    {
        const float4* wp = (const float4*)(W + tid * 32);
        #pragma unroll
        for (int i = 0; i < 8; i++) {
            float4 v = wp[i];
            int idx = tid * 32 + i * 4;
            int k = idx >> 6, n = idx & 63;
            float vv[4] = {v.x, v.y, v.z, v.w};
            #pragma unroll
            for (int j = 0; j < 4; j++) {
                __half hi = __float2half_rn(vv[j]);
                __half lo = __float2half_rn(vv[j] - __half2float(hi));
                Bhi[k * LDB + n + j] = hi;
                Blo[k * LDB + n + j] = lo;
            }
        }
    }
    __syncthreads();

    // ---- MMA: warp w owns rows w*16..+15, all 64 cols ----
    wmma::fragment<wmma::accumulator, 16, 16, 16, float> acc[4];
    #pragma unroll
    for (int n = 0; n < 4; n++) wmma::fill_fragment(acc[n], 0.0f);

    #pragma unroll
    for (int k = 0; k < 8; k++) {
        wmma::fragment<wmma::matrix_a, 16, 16, 16, __half, wmma::row_major> ahi, alo;
        wmma::load_matrix_sync(ahi, &Ahi[(wid * 16) * LDA + k * 16], LDA);
        wmma::load_matrix_sync(alo, &Alo[(wid * 16) * LDA + k * 16], LDA);
        #pragma unroll
        for (int n = 0; n < 4; n++) {
            wmma::fragment<wmma::matrix_b, 16, 16, 16, __half, wmma::row_major> bhi, blo;
            wmma::load_matrix_sync(bhi, &Bhi[(k * 16) * LDB + n * 16], LDB);
            wmma::load_matrix_sync(blo, &Blo[(k * 16) * LDB + n * 16], LDB);
            wmma::mma_sync(acc[n], ahi, bhi, acc[n]);
            wmma::mma_sync(acc[n], ahi, blo, acc[n]);
            wmma::mma_sync(acc[n], alo, bhi, acc[n]);
        }
    }

    __syncthreads();   // A-tile reads complete before aliasing Cs over it
    #pragma unroll
    for (int n = 0; n < 4; n++)
        wmma::store_matrix_sync(&Cs[(wid * 16) * LDC + n * 16], acc[n], LDC, wmma::mem_row_major);
    __syncthreads();

    // ---- epilogue: one thread per row; score dots fp32, Wh stored fp16 ----
    if (tid < GR) {
        const int row = row0 + tid;
        if (row < N_NODES) {
            const float* c = &Cs[tid * LDC];
            float sa[NH] = {0, 0, 0, 0}, sb[NH] = {0, 0, 0, 0};
            #pragma unroll
            for (int j = 0; j < OUT_C; j++) {
                const float v = c[j];
                const int hh = j >> 4;
                sa[hh] = fmaf(v, __ldg(&a_src[j]), sa[hh]);
                sb[hh] = fmaf(v, __ldg(&a_dst[j]), sb[hh]);
            }
            *(float4*)&g_sa[(size_t)row * NH] = make_float4(sa[0], sa[1], sa[2], sa[3]);
            *(float4*)&g_sb[(size_t)row * NH] = make_float4(sb[0], sb[1], sb[2], sb[3]);

            uint4* wout = (uint4*)&g_Wh[(size_t)row * OUT_C];
            #pragma unroll
            for (int q = 0; q < 8; q++) {
                uint4 u;
                __half2 p0 = __floats2half2_rn(c[q * 8 + 0], c[q * 8 + 1]);
                __half2 p1 = __floats2half2_rn(c[q * 8 + 2], c[q * 8 + 3]);
                __half2 p2 = __floats2half2_rn(c[q * 8 + 4], c[q * 8 + 5]);
                __half2 p3 = __floats2half2_rn(c[q * 8 + 6], c[q * 8 + 7]);
                ((__half2*)&u)[0] = p0; ((__half2*)&u)[1] = p1;
                ((__half2*)&u)[2] = p2; ((__half2*)&u)[3] = p3;
                wout[q] = u;
            }
        }
    }
}

// ---------------- edge kernel: 8 threads/edge, fp16 gather, shfl softmax -------
__global__ __launch_bounds__(256)
void edge_kernel(const void* __restrict__ ei_raw, float* __restrict__ out)
{
    const long long gt = (long long)blockIdx.x * blockDim.x + threadIdx.x;
    const int edge = (int)(gt >> 3);
    const int s    = (int)(gt & 7);
    if (edge >= E_EDGES) return;

    int src, dst;
    if (g_is64) {
        const long long* ei = (const long long*)ei_raw;
        src = (int)__ldg(&ei[edge]);
        dst = (int)__ldg(&ei[(size_t)E_EDGES + edge]);
    } else {
        const int* ei = (const int*)ei_raw;
        src = __ldg(&ei[edge]);
        dst = __ldg(&ei[(size_t)E_EDGES + edge]);
    }
    src = min(max(src, 0), N_NODES - 1);
    dst = min(max(dst, 0), N_NODES - 1);

    // this thread's head: cols s*8..s*8+7 all lie in head s>>1
    const int hh = s >> 1;
    float es = g_sa[(size_t)src * NH + hh] + g_sb[(size_t)dst * NH + hh];
    es = (es >= 0.0f) ? es : ALPHA * es;

    // softmax over the 4 heads within the 8-lane edge group ({s, s^2, s^4, s^6})
    float m = es;
    m = fmaxf(m, __shfl_xor_sync(0xffffffffu, m, 2));
    m = fmaxf(m, __shfl_xor_sync(0xffffffffu, m, 4));
    float x = __expf(es - m);
    float sum = x;
    sum += __shfl_xor_sync(0xffffffffu, sum, 2);
    sum += __shfl_xor_sync(0xffffffffu, sum, 4);
    const float att = x / sum;

    // gather 16B = 8 fp16 message values
    const uint4 wv = *(const uint4*)&g_Wh[(size_t)src * OUT_C + s * 8];
    float2 f0 = __half22float2(((const __half2*)&wv)[0]);
    float2 f1 = __half22float2(((const __half2*)&wv)[1]);
    float2 f2 = __half22float2(((const __half2*)&wv)[2]);
    float2 f3 = __half22float2(((const __half2*)&wv)[3]);

    float* dptr = out + (size_t)dst * OUT_C + s * 8;
    asm volatile("red.global.add.v4.f32 [%0], {%1,%2,%3,%4};"
                 :: "l"(dptr), "f"(f0.x * att), "f"(f0.y * att),
                    "f"(f1.x * att), "f"(f1.y * att)
                 : "memory");
    asm volatile("red.global.add.v4.f32 [%0], {%1,%2,%3,%4};"
                 :: "l"(dptr + 4), "f"(f2.x * att), "f"(f2.y * att),
                    "f"(f3.x * att), "f"(f3.y * att)
                 : "memory");
}

// ---------------- final ReLU (in place on d_out) ----------------
__global__ __launch_bounds__(256)
void relu_kernel(float4* __restrict__ out, int n4)
{
    const int i = blockIdx.x * blockDim.x + threadIdx.x;
    if (i < n4) {
        float4 v = out[i];
        v.x = fmaxf(v.x, 0.0f); v.y = fmaxf(v.y, 0.0f);
        v.z = fmaxf(v.z, 0.0f); v.w = fmaxf(v.w, 0.0f);
        out[i] = v;
    }
}

// ---------------- launch ----------------
extern "C" void kernel_launch(void* const* d_in, const int* in_sizes, int n_in,
                              void* d_out, int out_size)
{
    // size-based input identification with positional fallback
    const float* h     = nullptr;
    const void*  ei    = nullptr;
    const float* W     = nullptr;
    const float* a_src = nullptr;
    const float* a_dst = nullptr;
    for (int i = 0; i < n_in; i++) {
        const int s = in_sizes[i];
        if      (s == N_NODES * IN_F)  h  = (const float*)d_in[i];
        else if (s == 2 * E_EDGES)     ei = d_in[i];
        else if (s == IN_F * OUT_C)    W  = (const float*)d_in[i];
        else if (s == OUT_C) {
            if (!a_src) a_src = (const float*)d_in[i];
            else        a_dst = (const float*)d_in[i];
        }
    }
    if (!h || !ei || !W || !a_src || !a_dst) {
        h     = (const float*)d_in[0];
        ei    = d_in[1];
        W     = (const float*)d_in[2];
        a_src = (const float*)d_in[3];
        a_dst = (const float*)d_in[4];
    }
    float* out = (float*)d_out;

    detect_kernel<<<1, 1>>>(ei);

    cudaMemsetAsync(out, 0, (size_t)N_NODES * OUT_C * sizeof(float), 0);

    cudaFuncSetAttribute(gemm_kernel,
                         cudaFuncAttributeMaxDynamicSharedMemorySize,
                         GEMM_SMEM_BYTES);
    gemm_kernel<<<(N_NODES + GR - 1) / GR, 256, GEMM_SMEM_BYTES>>>(h, W, a_src, a_dst);

    const long long ethreads = (long long)E_EDGES * 8;
    edge_kernel<<<(int)((ethreads + 255) / 256), 256>>>(ei, out);

    const int n4 = N_NODES * OUT_C / 4;
    relu_kernel<<<(n4 + 255) / 256, 256>>>((float4*)out, n4);
}